// round 7
// baseline (speedup 1.0000x reference)
#include <cuda_runtime.h>
#include <cuda_fp16.h>
#include <cstdint>

#define NODES 32768
#define KNB   12
#define DIM   128
#define ROWS  (NODES * KNB)          // 393216
#define TROWS 96                     // tile rows = 8 nodes exactly
#define TNODES 8
#define NSUP  (ROWS / TROWS)         // 4096
#define GRID1 152

__device__ float g_agg[NODES * DIM];

__device__ __forceinline__ uint32_t smem_u32(const void* p) {
    uint32_t a;
    asm("{ .reg .u64 t; cvta.to.shared.u64 t, %1; cvt.u32.u64 %0, t; }"
        : "=r"(a) : "l"(p));
    return a;
}

#define LDSM4(r, addr) \
    asm volatile("ldmatrix.sync.aligned.m8n8.x4.shared.b16 {%0,%1,%2,%3}, [%4];" \
        : "=r"((r)[0]), "=r"((r)[1]), "=r"((r)[2]), "=r"((r)[3]) : "r"(addr))

#define MMA_F16(acc, a, b) \
    asm volatile("mma.sync.aligned.m16n8k16.row.col.f32.f16.f16.f32 " \
        "{%0,%1,%2,%3}, {%4,%5,%6,%7}, {%8,%9}, {%0,%1,%2,%3};" \
        : "+f"((acc)[0]), "+f"((acc)[1]), "+f"((acc)[2]), "+f"((acc)[3]) \
        : "r"((a)[0]), "r"((a)[1]), "r"((a)[2]), "r"((a)[3]), \
          "r"((b)[0]), "r"((b)[1]))

#define BAR_SYNC(id)    asm volatile("bar.sync %0, 512;"   :: "r"(id) : "memory")
#define BAR_ARRIVE(id)  asm volatile("bar.arrive %0, 512;" :: "r"(id) : "memory")
#define BAR_CONS()      asm volatile("bar.sync 5, 384;"    ::: "memory")

__device__ __forceinline__ uint32_t sw_off(int row, int chunk) {
    return (uint32_t)(row * 256 + ((chunk ^ (row & 7)) << 4));
}

// ---------------------------------------------------------------------------
// Fused kernel SMEM layout (bytes):
#define SM_W     0                  // w1^T fp16 swizzled (32KB)
#define SM_A0    32768              // feat fp16 tile buf0 (96x256B = 24KB)
#define SM_A1    57344
#define SM_R0    81920              // raw nbr fp32 tile buf0 (96x512B = 48KB)
#define SM_R1    131072
#define SM_MISC  180224
//   s_w1b[128] f32 @ +0,  s_w2[128] f32 @ +512,
//   s_lp[96*4] f32 @ +1024, s_p[96] f32 @ +2560
#define SMEM1    (SM_MISC + 2944)

#define BAR_READY0 1
#define BAR_READY1 2
#define BAR_FREE0  3
#define BAR_FREE1  4

// ---------------------------------------------------------------------------
// Fused: logits = LeakyReLU(feat@w1 + wgt*w1bias)@w2 ; softmax over K=12 ;
//        agg = sum_k p_k * nbr_k  -> g_agg
// 512 thr: warps 0-11 consumers (32x32 warp tiles, 3/SMSP), 12-15 producers.
// Double-buffered (feat fp16 + raw fp32 per buffer).
// ---------------------------------------------------------------------------
extern "C" __global__ void __launch_bounds__(512, 1)
fused_attn_kernel(const float* __restrict__ nbr,
                  const float* __restrict__ wgt,
                  const float* __restrict__ extra,
                  const float* __restrict__ w1,
                  const float* __restrict__ w2)
{
    extern __shared__ __align__(1024) char smem[];
    const int t    = threadIdx.x;
    const int lane = t & 31;
    const int w    = t >> 5;
    const uint32_t sb = smem_u32(smem);

    float* s_w1b = (float*)(smem + SM_MISC);
    float* s_w2  = s_w1b + 128;
    float* s_lp  = s_w2 + 128;       // [row*4 + wn]
    float* s_p   = s_lp + 96 * 4;    // normalized softmax probs [96]

    // ---- stage w1^T (Wt[n][k]) as fp16, swizzled (once) ----
    #pragma unroll 4
    for (int i = 0; i < 32; ++i) {
        int idx = t + i * 512;                 // 16384 = 128*128
        int n = idx >> 7, k = idx & 127;
        __half hx = __float2half_rn(w1[k * 128 + n]);
        uint32_t off = sw_off(n, k >> 3) + (k & 7) * 2;
        asm volatile("st.shared.u16 [%0], %1;" :: "r"(sb + SM_W + off),
                     "h"(__half_as_ushort(hx)));
    }
    if (t < 128) { s_w1b[t] = w1[128 * 128 + t]; s_w2[t] = w2[t]; }
    __syncthreads();

    if (w >= 12) {
        // ================= PRODUCER (warps 12-15, 128 threads) =================
        const int pt = t - 384;
        const float4* nbr4   = (const float4*)nbr;
        const float4* extra4 = (const float4*)extra;
        int it = 0;
        for (int sup = blockIdx.x; sup < NSUP; sup += GRID1, ++it) {
            const int b = it & 1;
            if (it >= 2) BAR_SYNC(BAR_FREE0 + b);
            const uint32_t aBuf = sb + (b ? SM_A1 : SM_A0);
            char* rBuf = smem + (b ? SM_R1 : SM_R0);
            const int row0 = sup * TROWS;
            #pragma unroll 4
            for (int i = 0; i < 24; ++i) {
                int idx  = pt + i * 128;       // 3072 float4 units = 96 rows x 32
                int row  = idx >> 5;
                int c4   = idx & 31;
                unsigned grow = (unsigned)(row0 + row);
                unsigned node = grow / KNB;
                float4 n = nbr4[(size_t)grow * 32 + c4];
                float4 e = extra4[(size_t)node * 32 + c4];
                // raw fp32 copy for the aggregation stage
                *(float4*)(rBuf + row * 512 + c4 * 16) = n;
                float x0 = n.x * e.x, x1 = n.y * e.y, x2 = n.z * e.z, x3 = n.w * e.w;
                uint32_t p01, p23;
                asm("cvt.rn.f16x2.f32 %0, %1, %2;" : "=r"(p01) : "f"(x1), "f"(x0));
                asm("cvt.rn.f16x2.f32 %0, %1, %2;" : "=r"(p23) : "f"(x3), "f"(x2));
                uint32_t off = sw_off(row, c4 >> 1) + (c4 & 1) * 8;
                asm volatile("st.shared.v2.b32 [%0], {%1,%2};"
                             :: "r"(aBuf + off), "r"(p01), "r"(p23));
            }
            BAR_ARRIVE(BAR_READY0 + b);
        }
    } else {
        // ================= CONSUMER (warps 0-11, 384 threads) =================
        const int wm = w >> 2;                 // 0..2 : rows [wm*32, +32)
        const int wn = w & 3;                  // 0..3 : cols [wn*32, +32)
        const int aRow = wm * 32 + (lane & 15);
        const int aCb  = lane >> 4;
        const int aXor = aRow & 7;
        const int bNl  = ((lane >> 4) << 3) + (lane & 7);
        const int bCb  = (lane >> 3) & 1;
        const int bXor = lane & 7;
        const uint32_t nBase = (uint32_t)((wn * 32 + bNl) * 256);
        const int grp = lane >> 2, qid = lane & 3;

        const unsigned long long C06 = 0x3F19999A3F19999Aull;   // {0.6f,0.6f}
        const unsigned long long C04 = 0x3ECCCCCD3ECCCCCDull;   // {0.4f,0.4f}
        const unsigned long long MSK = 0x7FFFFFFF7FFFFFFFull;

        // hoist B fragments for k-steps 0..3 (w1 is loop-invariant)
        uint32_t Bc[4][2][4];
        #pragma unroll
        for (int ks = 0; ks < 4; ++ks)
            #pragma unroll
            for (int j = 0; j < 2; ++j)
                LDSM4(Bc[ks][j], sb + SM_W + nBase + (uint32_t)(j * 4096)
                                 + (uint32_t)(((2 * ks + bCb) ^ bXor) << 4));

        int it = 0;
        for (int sup = blockIdx.x; sup < NSUP; sup += GRID1, ++it) {
            const int b = it & 1;
            BAR_SYNC(BAR_READY0 + b);
            const uint32_t aBase = sb + (b ? SM_A1 : SM_A0) + aRow * 256;
            const char* rBuf = smem + (b ? SM_R1 : SM_R0);
            const int row0  = sup * TROWS;
            const int node0 = sup * TNODES;

            float acc[2][4][4];
            #pragma unroll
            for (int mi = 0; mi < 2; ++mi)
                #pragma unroll
                for (int ni = 0; ni < 4; ++ni)
                    { acc[mi][ni][0]=acc[mi][ni][1]=acc[mi][ni][2]=acc[mi][ni][3]=0.f; }

            #pragma unroll
            for (int ks = 0; ks < 8; ++ks) {
                uint32_t a0[4], a1[4];
                uint32_t koffA = (uint32_t)(((2 * ks + aCb) ^ aXor) << 4);
                LDSM4(a0, aBase + koffA);
                LDSM4(a1, aBase + 4096 + koffA);
                #pragma unroll
                for (int j = 0; j < 2; ++j) {
                    uint32_t bt[4];
                    const uint32_t* bp;
                    if (ks < 4) {
                        bp = Bc[ks][j];
                    } else {
                        LDSM4(bt, sb + SM_W + nBase + (uint32_t)(j * 4096)
                                  + (uint32_t)(((2 * ks + bCb) ^ bXor) << 4));
                        bp = bt;
                    }
                    MMA_F16(acc[0][2*j],   a0, bp);
                    MMA_F16(acc[0][2*j+1], a0, bp + 2);
                    MMA_F16(acc[1][2*j],   a1, bp);
                    MMA_F16(acc[1][2*j+1], a1, bp + 2);
                }
            }

            // ---- epilogue: bias + leaky(0.6v+0.4|v|) + dot(w2), f32x2 packed ----
            #pragma unroll
            for (int mi = 0; mi < 2; ++mi) {
                const int rowA = wm * 32 + mi * 16 + grp;
                const float wrA = __ldg(&wgt[row0 + rowA]);
                const float wrB = __ldg(&wgt[row0 + rowA + 8]);
                unsigned long long wA2, wB2, pa2 = 0ull, pb2 = 0ull;
                asm("mov.b64 %0,{%1,%1};" : "=l"(wA2) : "r"(__float_as_uint(wrA)));
                asm("mov.b64 %0,{%1,%1};" : "=l"(wB2) : "r"(__float_as_uint(wrB)));
                #pragma unroll
                for (int ni = 0; ni < 4; ++ni) {
                    int c = wn * 32 + ni * 8 + qid * 2;
                    unsigned long long b01 = *(const unsigned long long*)(s_w1b + c);
                    unsigned long long u01 = *(const unsigned long long*)(s_w2 + c);
                    unsigned long long a01, a23, v, av, l;
                    asm("mov.b64 %0,{%1,%2};" : "=l"(a01)
                        : "r"(__float_as_uint(acc[mi][ni][0])),
                          "r"(__float_as_uint(acc[mi][ni][1])));
                    asm("mov.b64 %0,{%1,%2};" : "=l"(a23)
                        : "r"(__float_as_uint(acc[mi][ni][2])),
                          "r"(__float_as_uint(acc[mi][ni][3])));
                    asm("fma.rn.f32x2 %0,%1,%2,%3;" : "=l"(v) : "l"(wA2), "l"(b01), "l"(a01));
                    av = v & MSK;
                    asm("mul.rn.f32x2 %0,%1,%2;" : "=l"(l) : "l"(v), "l"(C06));
                    asm("fma.rn.f32x2 %0,%1,%2,%0;" : "+l"(l) : "l"(av), "l"(C04));
                    asm("fma.rn.f32x2 %0,%1,%2,%0;" : "+l"(pa2) : "l"(l), "l"(u01));
                    asm("fma.rn.f32x2 %0,%1,%2,%3;" : "=l"(v) : "l"(wB2), "l"(b01), "l"(a23));
                    av = v & MSK;
                    asm("mul.rn.f32x2 %0,%1,%2;" : "=l"(l) : "l"(v), "l"(C06));
                    asm("fma.rn.f32x2 %0,%1,%2,%0;" : "+l"(l) : "l"(av), "l"(C04));
                    asm("fma.rn.f32x2 %0,%1,%2,%0;" : "+l"(pb2) : "l"(l), "l"(u01));
                }
                uint32_t lo, hi;
                asm("mov.b64 {%0,%1},%2;" : "=r"(lo), "=r"(hi) : "l"(pa2));
                float pa = __uint_as_float(lo) + __uint_as_float(hi);
                asm("mov.b64 {%0,%1},%2;" : "=r"(lo), "=r"(hi) : "l"(pb2));
                float pb = __uint_as_float(lo) + __uint_as_float(hi);
                pa += __shfl_xor_sync(0xffffffffu, pa, 1);
                pa += __shfl_xor_sync(0xffffffffu, pa, 2);
                pb += __shfl_xor_sync(0xffffffffu, pb, 1);
                pb += __shfl_xor_sync(0xffffffffu, pb, 2);
                if (qid == 0) {
                    s_lp[rowA * 4 + wn]       = pa;
                    s_lp[(rowA + 8) * 4 + wn] = pb;
                }
            }
            BAR_CONS();

            // ---- per-node softmax (8 nodes, 1 thread each) ----
            if (t < TNODES) {
                const int base = t * KNB;
                float lg[KNB];
                float m = -1e30f;
                #pragma unroll
                for (int k = 0; k < KNB; ++k) {
                    const float* p4 = s_lp + (base + k) * 4;
                    float v = (p4[0] + p4[1]) + (p4[2] + p4[3]);
                    lg[k] = v;
                    m = fmaxf(m, v);
                }
                float sum = 0.f;
                #pragma unroll
                for (int k = 0; k < KNB; ++k) { lg[k] = __expf(lg[k] - m); sum += lg[k]; }
                const float inv = 1.0f / sum;
                #pragma unroll
                for (int k = 0; k < KNB; ++k) s_p[base + k] = lg[k] * inv;
            }
            BAR_CONS();

            // ---- aggregation: 8 nodes x 32 float4-cols over 256 threads ----
            if (t < 256) {
                const int node = t >> 5, c4 = t & 31;
                const char* rbase = rBuf + (node * KNB) * 512 + c4 * 16;
                float4 agg = make_float4(0.f, 0.f, 0.f, 0.f);
                #pragma unroll
                for (int k = 0; k < KNB; ++k) {
                    float pk = s_p[node * KNB + k];
                    float4 r = *(const float4*)(rbase + k * 512);
                    agg.x += pk * r.x; agg.y += pk * r.y;
                    agg.z += pk * r.z; agg.w += pk * r.w;
                }
                ((float4*)g_agg)[(size_t)(node0 + node) * 32 + c4] = agg;
            }
            BAR_ARRIVE(BAR_FREE0 + b);
        }
    }
}

// ---------------------------------------------------------------------------
// K3: out = relu(concat(self, agg) @ w3), single-pass fp16 (unchanged r6)
// ---------------------------------------------------------------------------
#define SM3_W   0
#define SM3_A   65536
#define SMEM3   (65536 + 32768)
#define NT3     (NODES / 128)      // 256 tiles

extern "C" __global__ void __launch_bounds__(256, 1)
out_gemm_kernel(const float* __restrict__ selfv,
                const float* __restrict__ w3,
                float* __restrict__ out)
{
    extern __shared__ __align__(1024) char smem[];
    const int t    = threadIdx.x;
    const int lane = t & 31;
    const int w    = t >> 5;
    const uint32_t sb = smem_u32(smem);

    #pragma unroll 4
    for (int i = 0; i < 128; ++i) {
        int idx = t + i * 256;                 // 32768 = 256*128
        int n = idx >> 8, k = idx & 255;
        __half hx = __float2half_rn(w3[k * 128 + n]);
        uint32_t off = (uint32_t)(n * 512 + (((k >> 3) ^ (n & 7)) << 4) + (k & 7) * 2);
        asm volatile("st.shared.u16 [%0], %1;" :: "r"(sb + SM3_W + off),
                     "h"(__half_as_ushort(hx)));
    }

    const int wm = w & 3;
    const int wn = w >> 2;
    const int aRow = wm * 32 + (lane & 15);
    const int aCb  = lane >> 4;
    const int aXor = aRow & 7;
    const int bNl  = ((lane >> 4) << 3) + (lane & 7);
    const int bCb  = (lane >> 3) & 1;
    const int bXor = lane & 7;
    const uint32_t nBase = (uint32_t)((wn * 64 + bNl) * 512);
    const uint32_t aBase = sb + SM3_A + aRow * 256;

    for (int tile = blockIdx.x; tile < NT3; tile += 128) {
        const int r0 = tile * 128;

        float acc[2][8][4];
        #pragma unroll
        for (int mi = 0; mi < 2; ++mi)
            #pragma unroll
            for (int ni = 0; ni < 8; ++ni)
                { acc[mi][ni][0]=acc[mi][ni][1]=acc[mi][ni][2]=acc[mi][ni][3]=0.f; }

        #pragma unroll 1
        for (int half = 0; half < 2; ++half) {
            __syncthreads();
            const float4* src = (const float4*)(half ? (const float*)g_agg : selfv);
            #pragma unroll 4
            for (int i = 0; i < 16; ++i) {
                int idx = t + i * 256;
                int row = idx >> 5;
                int c4  = idx & 31;
                float4 v = src[(size_t)(r0 + row) * 32 + c4];
                uint32_t p01, p23;
                asm("cvt.rn.f16x2.f32 %0, %1, %2;" : "=r"(p01) : "f"(v.y), "f"(v.x));
                asm("cvt.rn.f16x2.f32 %0, %1, %2;" : "=r"(p23) : "f"(v.w), "f"(v.z));
                uint32_t off = sw_off(row, c4 >> 1) + (c4 & 1) * 8;
                asm volatile("st.shared.v2.b32 [%0], {%1,%2};"
                             :: "r"(sb + SM3_A + off), "r"(p01), "r"(p23));
            }
            __syncthreads();

            #pragma unroll
            for (int ks = 0; ks < 8; ++ks) {
                uint32_t a0[4], a1[4];
                uint32_t koffA = (uint32_t)(((2 * ks + aCb) ^ aXor) << 4);
                LDSM4(a0, aBase + koffA);
                LDSM4(a1, aBase + 4096 + koffA);
                const uint32_t kc = (uint32_t)(((half * 16 + 2 * ks + bCb) ^ bXor) << 4);
                #pragma unroll
                for (int j = 0; j < 4; ++j) {
                    uint32_t bh[4];
                    LDSM4(bh, sb + SM3_W + nBase + (uint32_t)(j * 16 * 512) + kc);
                    MMA_F16(acc[0][2*j],   a0, bh);
                    MMA_F16(acc[0][2*j+1], a0, bh + 2);
                    MMA_F16(acc[1][2*j],   a1, bh);
                    MMA_F16(acc[1][2*j+1], a1, bh + 2);
                }
            }
        }

        const int grp = lane >> 2, qid = lane & 3;
        #pragma unroll
        for (int mi = 0; mi < 2; ++mi) {
            const int rowg = r0 + wm * 32 + mi * 16 + grp;
            #pragma unroll
            for (int ni = 0; ni < 8; ++ni) {
                int col = wn * 64 + ni * 8 + qid * 2;
                float2 o0, o1;
                o0.x = fmaxf(acc[mi][ni][0], 0.f); o0.y = fmaxf(acc[mi][ni][1], 0.f);
                o1.x = fmaxf(acc[mi][ni][2], 0.f); o1.y = fmaxf(acc[mi][ni][3], 0.f);
                *(float2*)(out + (size_t)rowg * 128 + col)       = o0;
                *(float2*)(out + (size_t)(rowg + 8) * 128 + col) = o1;
            }
        }
    }
}

// ---------------------------------------------------------------------------
extern "C" void kernel_launch(void* const* d_in, const int* in_sizes, int n_in,
                              void* d_out, int out_size)
{
    int idx = 0;
    const float* selfv = (const float*)d_in[idx++];
    const float* nbr   = (const float*)d_in[idx++];
    if (idx < n_in && in_sizes[idx] == 1) idx++;   // batch_size scalar
    idx++;                                         // masks (unused)
    const float* wgt   = (const float*)d_in[idx++];
    const float* extra = (const float*)d_in[idx++];
    const float* w1    = (const float*)d_in[idx++];
    const float* w2    = (const float*)d_in[idx++];
    const float* w3    = (const float*)d_in[idx++];
    float* out = (float*)d_out;

    cudaFuncSetAttribute(fused_attn_kernel, cudaFuncAttributeMaxDynamicSharedMemorySize, SMEM1);
    cudaFuncSetAttribute(out_gemm_kernel,   cudaFuncAttributeMaxDynamicSharedMemorySize, SMEM3);

    fused_attn_kernel<<<GRID1, 512, SMEM1>>>(nbr, wgt, extra, w1, w2);
    out_gemm_kernel<<<128, 256, SMEM3>>>(selfv, w3, out);
    (void)out_size; (void)n_in;
}

// round 8
// speedup vs baseline: 1.1911x; 1.1911x over previous
#include <cuda_runtime.h>
#include <cuda_fp16.h>
#include <cstdint>

#define NODES 32768
#define KNB   12
#define DIM   128
#define ROWS  (NODES * KNB)          // 393216
#define NSUP  (ROWS / 128)           // 3072 row-tiles of 128
#define GRID1 152

__device__ float g_logits[ROWS];

__device__ __forceinline__ uint32_t smem_u32(const void* p) {
    uint32_t a;
    asm("{ .reg .u64 t; cvta.to.shared.u64 t, %1; cvt.u32.u64 %0, t; }"
        : "=r"(a) : "l"(p));
    return a;
}

#define LDSM4(r, addr) \
    asm volatile("ldmatrix.sync.aligned.m8n8.x4.shared.b16 {%0,%1,%2,%3}, [%4];" \
        : "=r"((r)[0]), "=r"((r)[1]), "=r"((r)[2]), "=r"((r)[3]) : "r"(addr))

#define MMA_F16(acc, a, b) \
    asm volatile("mma.sync.aligned.m16n8k16.row.col.f32.f16.f16.f32 " \
        "{%0,%1,%2,%3}, {%4,%5,%6,%7}, {%8,%9}, {%0,%1,%2,%3};" \
        : "+f"((acc)[0]), "+f"((acc)[1]), "+f"((acc)[2]), "+f"((acc)[3]) \
        : "r"((a)[0]), "r"((a)[1]), "r"((a)[2]), "r"((a)[3]), \
          "r"((b)[0]), "r"((b)[1]))

#define BAR_SYNC(id)    asm volatile("bar.sync %0, 512;"   :: "r"(id) : "memory")
#define BAR_ARRIVE(id)  asm volatile("bar.arrive %0, 512;" :: "r"(id) : "memory")
#define BAR_SYNC_C(id)  asm volatile("bar.sync %0, 256;"   :: "r"(id) : "memory")

__device__ __forceinline__ uint32_t sw_off(int row, int chunk) {
    return (uint32_t)(row * 256 + ((chunk ^ (row & 7)) << 4));
}

// ===========================================================================
// K1 (EXACT round-6 code): logits = LeakyReLU(feat@w1 + wgt*w1bias)@w2
// Single-pass fp16 mma.sync, warp-specialized, triple-buffered.
// ===========================================================================
#define SM_W     0
#define SM_A0    32768
#define SM_A1    65536
#define SM_A2    98304
#define SM_MISC  131072
#define SMEM1    (SM_MISC + 512 + 512 + 1024)

#define BAR_READY0 1
#define BAR_READY1 2
#define BAR_READY2 3
#define BAR_FREE0  4
#define BAR_FREE1  5
#define BAR_FREE2  6
#define BAR_CONS   7

extern "C" __global__ void __launch_bounds__(512, 1)
logits_kernel(const float* __restrict__ nbr,
              const float* __restrict__ wgt,
              const float* __restrict__ extra,
              const float* __restrict__ w1,
              const float* __restrict__ w2)
{
    extern __shared__ __align__(1024) char smem[];
    const int t    = threadIdx.x;
    const int lane = t & 31;
    const int w    = t >> 5;
    const uint32_t sb = smem_u32(smem);

    float* s_w1b  = (float*)(smem + SM_MISC);
    float* s_w2   = s_w1b + 128;
    float* s_part = s_w2 + 128;

    #pragma unroll 4
    for (int i = 0; i < 32; ++i) {
        int idx = t + i * 512;
        int n = idx >> 7, k = idx & 127;
        __half hx = __float2half_rn(w1[k * 128 + n]);
        uint32_t off = sw_off(n, k >> 3) + (k & 7) * 2;
        asm volatile("st.shared.u16 [%0], %1;" :: "r"(sb + SM_W + off),
                     "h"(__half_as_ushort(hx)));
    }
    if (t < 128) { s_w1b[t] = w1[128 * 128 + t]; s_w2[t] = w2[t]; }
    __syncthreads();

    if (w >= 8) {
        const int pt = t & 255;
        const float4* nbr4   = (const float4*)nbr;
        const float4* extra4 = (const float4*)extra;
        int it = 0;
        for (int sup = blockIdx.x; sup < NSUP; sup += GRID1, ++it) {
            const int b = (it >= 3) ? (it % 3) : it;
            if (it >= 3) BAR_SYNC(BAR_FREE0 + b);
            const uint32_t aBuf = sb + SM_A0 + b * 32768;
            const int row0 = sup * 128;
            #pragma unroll 4
            for (int i = 0; i < 16; ++i) {
                int idx  = pt + i * 256;
                int row  = idx >> 5;
                int c4   = idx & 31;
                unsigned grow = (unsigned)(row0 + row);
                unsigned node = grow / KNB;
                float4 n = nbr4[(size_t)grow * 32 + c4];
                float4 e = extra4[(size_t)node * 32 + c4];
                float x0 = n.x * e.x, x1 = n.y * e.y, x2 = n.z * e.z, x3 = n.w * e.w;
                uint32_t p01, p23;
                asm("cvt.rn.f16x2.f32 %0, %1, %2;" : "=r"(p01) : "f"(x1), "f"(x0));
                asm("cvt.rn.f16x2.f32 %0, %1, %2;" : "=r"(p23) : "f"(x3), "f"(x2));
                uint32_t off = sw_off(row, c4 >> 1) + (c4 & 1) * 8;
                asm volatile("st.shared.v2.b32 [%0], {%1,%2};"
                             :: "r"(aBuf + off), "r"(p01), "r"(p23));
            }
            BAR_ARRIVE(BAR_READY0 + b);
        }
    } else {
        const int wm = w & 3;
        const int wn = w >> 2;
        const int aRow = wm * 32 + (lane & 15);
        const int aCb  = lane >> 4;
        const int aXor = aRow & 7;
        const int bNl  = ((lane >> 4) << 3) + (lane & 7);
        const int bCb  = (lane >> 3) & 1;
        const int bXor = lane & 7;
        const uint32_t nBase = (uint32_t)((wn * 64 + bNl) * 256);

        int it = 0;
        for (int sup = blockIdx.x; sup < NSUP; sup += GRID1, ++it) {
            const int b = (it >= 3) ? (it % 3) : it;
            BAR_SYNC(BAR_READY0 + b);
            const uint32_t aBase = sb + SM_A0 + b * 32768 + aRow * 256;
            const int row0 = sup * 128;

            float acc[2][8][4];
            #pragma unroll
            for (int mi = 0; mi < 2; ++mi)
                #pragma unroll
                for (int ni = 0; ni < 8; ++ni)
                    { acc[mi][ni][0]=acc[mi][ni][1]=acc[mi][ni][2]=acc[mi][ni][3]=0.f; }

            #pragma unroll
            for (int ks = 0; ks < 8; ++ks) {
                uint32_t a0[4], a1[4];
                uint32_t koffA = (uint32_t)(((2 * ks + aCb) ^ aXor) << 4);
                LDSM4(a0, aBase + koffA);
                LDSM4(a1, aBase + 4096 + koffA);
                uint32_t kc = (uint32_t)(((2 * ks + bCb) ^ bXor) << 4);
                #pragma unroll
                for (int j = 0; j < 4; ++j) {
                    uint32_t bh[4];
                    LDSM4(bh, sb + SM_W + nBase + (uint32_t)(j * 16 * 256) + kc);
                    MMA_F16(acc[0][2*j],   a0, bh);
                    MMA_F16(acc[0][2*j+1], a0, bh + 2);
                    MMA_F16(acc[1][2*j],   a1, bh);
                    MMA_F16(acc[1][2*j+1], a1, bh + 2);
                }
            }
            BAR_ARRIVE(BAR_FREE0 + b);

            const int grp = lane >> 2, qid = lane & 3;
            #pragma unroll
            for (int mi = 0; mi < 2; ++mi) {
                const int rowA = wm * 32 + mi * 16 + grp;
                const float wrA = __ldg(&wgt[row0 + rowA]);
                const float wrB = __ldg(&wgt[row0 + rowA + 8]);
                float pa = 0.f, pb = 0.f;
                #pragma unroll
                for (int ni = 0; ni < 8; ++ni) {
                    int c = wn * 64 + ni * 8 + qid * 2;
                    float b0 = s_w1b[c], b1 = s_w1b[c + 1];
                    float u0 = s_w2[c],  u1 = s_w2[c + 1];
                    float v;
                    v = acc[mi][ni][0] + wrA * b0; v = (v >= 0.f) ? v : 0.2f * v; pa += v * u0;
                    v = acc[mi][ni][1] + wrA * b1; v = (v >= 0.f) ? v : 0.2f * v; pa += v * u1;
                    v = acc[mi][ni][2] + wrB * b0; v = (v >= 0.f) ? v : 0.2f * v; pb += v * u0;
                    v = acc[mi][ni][3] + wrB * b1; v = (v >= 0.f) ? v : 0.2f * v; pb += v * u1;
                }
                pa += __shfl_xor_sync(0xffffffffu, pa, 1);
                pa += __shfl_xor_sync(0xffffffffu, pa, 2);
                pb += __shfl_xor_sync(0xffffffffu, pb, 1);
                pb += __shfl_xor_sync(0xffffffffu, pb, 2);
                if (qid == 0) {
                    s_part[rowA * 2 + wn]       = pa;
                    s_part[(rowA + 8) * 2 + wn] = pb;
                }
            }
            BAR_SYNC_C(BAR_CONS);
            if (wn == 0) {
                const int row = wm * 32 + lane;
                g_logits[row0 + row] = s_part[row * 2] + s_part[row * 2 + 1];
            }
            BAR_SYNC_C(BAR_CONS);
        }
    }
}

// ===========================================================================
// K23 fused: per 128-node tile:
//   softmax(g_logits) -> p ; A = [fp16(self) | fp16(sum_k p*nbr)] ;
//   out = relu(A @ w3^T fp16)
// Persistent grid 152, 256 threads. A rows 512B (256 fp16 k), XOR swizzled.
// ===========================================================================
#define SM23_W  0                   // w3^T fp16 (64KB)
#define SM23_A  65536               // A fp16 tile (64KB)
#define SM23_P  131072              // probs 128*12 f32 (6KB)
#define SMEM23  (131072 + 6144)
#define NT23    (NODES / 128)       // 256 tiles

extern "C" __global__ void __launch_bounds__(256, 1)
fused_out_kernel(const float* __restrict__ nbr,
                 const float* __restrict__ selfv,
                 const float* __restrict__ w3,
                 float* __restrict__ out)
{
    extern __shared__ __align__(1024) char smem[];
    const int t    = threadIdx.x;
    const int lane = t & 31;
    const int w    = t >> 5;
    const uint32_t sb = smem_u32(smem);
    float* s_p = (float*)(smem + SM23_P);

    // ---- stage w3^T (Wt[n][k], k 0..255) fp16, swizzled (once) ----
    #pragma unroll 4
    for (int i = 0; i < 128; ++i) {
        int idx = t + i * 256;                 // 32768 = 256*128
        int n = idx >> 8, k = idx & 255;
        __half hx = __float2half_rn(w3[k * 128 + n]);
        uint32_t off = (uint32_t)(n * 512 + (((k >> 3) ^ (n & 7)) << 4) + (k & 7) * 2);
        asm volatile("st.shared.u16 [%0], %1;" :: "r"(sb + SM23_W + off),
                     "h"(__half_as_ushort(hx)));
    }

    const int wm = w & 3;
    const int wn = w >> 2;
    const int aRow = wm * 32 + (lane & 15);
    const int aCb  = lane >> 4;
    const int aXor = aRow & 7;
    const int bNl  = ((lane >> 4) << 3) + (lane & 7);
    const int bCb  = (lane >> 3) & 1;
    const int bXor = lane & 7;
    const uint32_t nBase = (uint32_t)((wn * 64 + bNl) * 512);
    const uint32_t aBase = sb + SM23_A + aRow * 512;

    const float4* nbr4  = (const float4*)nbr;
    const float4* self4 = (const float4*)selfv;

    for (int tile = blockIdx.x; tile < NT23; tile += GRID1) {
        const int node0 = tile * 128;
        __syncthreads();                        // A safe to overwrite

        // ---- softmax for 128 nodes (threads 0..127) ----
        if (t < 128) {
            const int base = (node0 + t) * KNB;
            float lg[KNB];
            float m = -1e30f;
            #pragma unroll
            for (int k = 0; k < KNB; ++k) { lg[k] = g_logits[base + k]; m = fmaxf(m, lg[k]); }
            float sum = 0.f;
            #pragma unroll
            for (int k = 0; k < KNB; ++k) { lg[k] = __expf(lg[k] - m); sum += lg[k]; }
            const float inv = 1.0f / sum;
            #pragma unroll
            for (int k = 0; k < KNB; ++k) s_p[t * KNB + k] = lg[k] * inv;
        }

        // ---- self -> A[k 0..127] fp16 swizzled ----
        #pragma unroll 4
        for (int i = 0; i < 16; ++i) {
            int idx = t + i * 256;              // 4096 = 128 rows x 32 c4
            int row = idx >> 5;
            int c4  = idx & 31;
            float4 v = self4[(size_t)(node0 + row) * 32 + c4];
            uint32_t p01, p23;
            asm("cvt.rn.f16x2.f32 %0, %1, %2;" : "=r"(p01) : "f"(v.y), "f"(v.x));
            asm("cvt.rn.f16x2.f32 %0, %1, %2;" : "=r"(p23) : "f"(v.w), "f"(v.z));
            uint32_t off = (uint32_t)(row * 512 + (((c4 >> 1) ^ (row & 7)) << 4)
                                      + (c4 & 1) * 8);
            asm volatile("st.shared.v2.b32 [%0], {%1,%2};"
                         :: "r"(sb + SM23_A + off), "r"(p01), "r"(p23));
        }
        __syncthreads();                        // probs ready

        // ---- agg -> A[k 128..255]: each warp handles one node per pass ----
        #pragma unroll 1
        for (int i = 0; i < 16; ++i) {
            int idx = t + i * 256;              // 4096 = 128 nodes x 32 c4
            int row = idx >> 5;                 // node-local (warp-uniform)
            int c4  = idx & 31;
            const float* pp = s_p + row * KNB;
            const float4* nb = nbr4 + ((size_t)(node0 + row) * KNB) * 32 + c4;
            float4 agg = make_float4(0.f, 0.f, 0.f, 0.f);
            #pragma unroll
            for (int k = 0; k < KNB; ++k) {
                float pk = pp[k];
                float4 r = nb[k * 32];
                agg.x += pk * r.x; agg.y += pk * r.y;
                agg.z += pk * r.z; agg.w += pk * r.w;
            }
            uint32_t p01, p23;
            asm("cvt.rn.f16x2.f32 %0, %1, %2;" : "=r"(p01) : "f"(agg.y), "f"(agg.x));
            asm("cvt.rn.f16x2.f32 %0, %1, %2;" : "=r"(p23) : "f"(agg.w), "f"(agg.z));
            uint32_t off = (uint32_t)(row * 512 + ((((c4 >> 1) + 16) ^ (row & 7)) << 4)
                                      + (c4 & 1) * 8);
            asm volatile("st.shared.v2.b32 [%0], {%1,%2};"
                         :: "r"(sb + SM23_A + off), "r"(p01), "r"(p23));
        }
        __syncthreads();                        // A complete

        // ---- GEMM 128x128x256 fp16, warp tile 32 rows x 64 cols ----
        float acc[2][8][4];
        #pragma unroll
        for (int mi = 0; mi < 2; ++mi)
            #pragma unroll
            for (int ni = 0; ni < 8; ++ni)
                { acc[mi][ni][0]=acc[mi][ni][1]=acc[mi][ni][2]=acc[mi][ni][3]=0.f; }

        #pragma unroll
        for (int ks = 0; ks < 16; ++ks) {
            uint32_t a0[4], a1[4];
            uint32_t koffA = (uint32_t)(((2 * ks + aCb) ^ aXor) << 4);
            LDSM4(a0, aBase + koffA);
            LDSM4(a1, aBase + 8192 + koffA);    // rows +16 (512B rows)
            const uint32_t kc = (uint32_t)(((2 * ks + bCb) ^ bXor) << 4);
            #pragma unroll
            for (int j = 0; j < 4; ++j) {
                uint32_t bh[4];
                LDSM4(bh, sb + SM23_W + nBase + (uint32_t)(j * 16 * 512) + kc);
                MMA_F16(acc[0][2*j],   a0, bh);
                MMA_F16(acc[0][2*j+1], a0, bh + 2);
                MMA_F16(acc[1][2*j],   a1, bh);
                MMA_F16(acc[1][2*j+1], a1, bh + 2);
            }
        }

        // ---- relu + store ----
        const int grp = lane >> 2, qid = lane & 3;
        #pragma unroll
        for (int mi = 0; mi < 2; ++mi) {
            const int rowg = node0 + wm * 32 + mi * 16 + grp;
            #pragma unroll
            for (int ni = 0; ni < 8; ++ni) {
                int col = wn * 64 + ni * 8 + qid * 2;
                float2 o0, o1;
                o0.x = fmaxf(acc[mi][ni][0], 0.f); o0.y = fmaxf(acc[mi][ni][1], 0.f);
                o1.x = fmaxf(acc[mi][ni][2], 0.f); o1.y = fmaxf(acc[mi][ni][3], 0.f);
                *(float2*)(out + (size_t)rowg * 128 + col)       = o0;
                *(float2*)(out + (size_t)(rowg + 8) * 128 + col) = o1;
            }
        }
    }
}

// ---------------------------------------------------------------------------
extern "C" void kernel_launch(void* const* d_in, const int* in_sizes, int n_in,
                              void* d_out, int out_size)
{
    int idx = 0;
    const float* selfv = (const float*)d_in[idx++];
    const float* nbr   = (const float*)d_in[idx++];
    if (idx < n_in && in_sizes[idx] == 1) idx++;   // batch_size scalar
    idx++;                                         // masks (unused)
    const float* wgt   = (const float*)d_in[idx++];
    const float* extra = (const float*)d_in[idx++];
    const float* w1    = (const float*)d_in[idx++];
    const float* w2    = (const float*)d_in[idx++];
    const float* w3    = (const float*)d_in[idx++];
    float* out = (float*)d_out;

    cudaFuncSetAttribute(logits_kernel,    cudaFuncAttributeMaxDynamicSharedMemorySize, SMEM1);
    cudaFuncSetAttribute(fused_out_kernel, cudaFuncAttributeMaxDynamicSharedMemorySize, SMEM23);

    logits_kernel<<<GRID1, 512, SMEM1>>>(nbr, wgt, extra, w1, w2);
    fused_out_kernel<<<GRID1, 256, SMEM23>>>(nbr, selfv, w3, out);
    (void)out_size; (void)n_in;
}

// round 9
// speedup vs baseline: 1.2390x; 1.0402x over previous
#include <cuda_runtime.h>
#include <cuda_fp16.h>
#include <cstdint>

#define NODES 32768
#define KNB   12
#define DIM   128
#define ROWS  (NODES * KNB)          // 393216
#define NSUP  (ROWS / 128)           // 3072 row-tiles of 128
#define GRID1 152

__device__ float g_logits[ROWS];

__device__ __forceinline__ uint32_t smem_u32(const void* p) {
    uint32_t a;
    asm("{ .reg .u64 t; cvta.to.shared.u64 t, %1; cvt.u32.u64 %0, t; }"
        : "=r"(a) : "l"(p));
    return a;
}

#define LDSM4(r, addr) \
    asm volatile("ldmatrix.sync.aligned.m8n8.x4.shared.b16 {%0,%1,%2,%3}, [%4];" \
        : "=r"((r)[0]), "=r"((r)[1]), "=r"((r)[2]), "=r"((r)[3]) : "r"(addr))

#define MMA_F16(acc, a, b) \
    asm volatile("mma.sync.aligned.m16n8k16.row.col.f32.f16.f16.f32 " \
        "{%0,%1,%2,%3}, {%4,%5,%6,%7}, {%8,%9}, {%0,%1,%2,%3};" \
        : "+f"((acc)[0]), "+f"((acc)[1]), "+f"((acc)[2]), "+f"((acc)[3]) \
        : "r"((a)[0]), "r"((a)[1]), "r"((a)[2]), "r"((a)[3]), \
          "r"((b)[0]), "r"((b)[1]))

#define BAR_SYNC(id)    asm volatile("bar.sync %0, 512;"   :: "r"(id) : "memory")
#define BAR_ARRIVE(id)  asm volatile("bar.arrive %0, 512;" :: "r"(id) : "memory")
#define BAR_SYNC_C(id)  asm volatile("bar.sync %0, 256;"   :: "r"(id) : "memory")

__device__ __forceinline__ uint32_t sw_off(int row, int chunk) {
    return (uint32_t)(row * 256 + ((chunk ^ (row & 7)) << 4));
}

// ===========================================================================
// K1 (EXACT round-6 code): logits = LeakyReLU(feat@w1 + wgt*w1bias)@w2
// ===========================================================================
#define SM_W     0
#define SM_A0    32768
#define SM_A1    65536
#define SM_A2    98304
#define SM_MISC  131072
#define SMEM1    (SM_MISC + 512 + 512 + 1024)

#define BAR_READY0 1
#define BAR_READY1 2
#define BAR_READY2 3
#define BAR_FREE0  4
#define BAR_FREE1  5
#define BAR_FREE2  6
#define BAR_CONS   7

extern "C" __global__ void __launch_bounds__(512, 1)
logits_kernel(const float* __restrict__ nbr,
              const float* __restrict__ wgt,
              const float* __restrict__ extra,
              const float* __restrict__ w1,
              const float* __restrict__ w2)
{
    extern __shared__ __align__(1024) char smem[];
    const int t    = threadIdx.x;
    const int lane = t & 31;
    const int w    = t >> 5;
    const uint32_t sb = smem_u32(smem);

    float* s_w1b  = (float*)(smem + SM_MISC);
    float* s_w2   = s_w1b + 128;
    float* s_part = s_w2 + 128;

    #pragma unroll 4
    for (int i = 0; i < 32; ++i) {
        int idx = t + i * 512;
        int n = idx >> 7, k = idx & 127;
        __half hx = __float2half_rn(w1[k * 128 + n]);
        uint32_t off = sw_off(n, k >> 3) + (k & 7) * 2;
        asm volatile("st.shared.u16 [%0], %1;" :: "r"(sb + SM_W + off),
                     "h"(__half_as_ushort(hx)));
    }
    if (t < 128) { s_w1b[t] = w1[128 * 128 + t]; s_w2[t] = w2[t]; }
    __syncthreads();

    if (w >= 8) {
        const int pt = t & 255;
        const float4* nbr4   = (const float4*)nbr;
        const float4* extra4 = (const float4*)extra;
        int it = 0;
        for (int sup = blockIdx.x; sup < NSUP; sup += GRID1, ++it) {
            const int b = (it >= 3) ? (it % 3) : it;
            if (it >= 3) BAR_SYNC(BAR_FREE0 + b);
            const uint32_t aBuf = sb + SM_A0 + b * 32768;
            const int row0 = sup * 128;
            #pragma unroll 4
            for (int i = 0; i < 16; ++i) {
                int idx  = pt + i * 256;
                int row  = idx >> 5;
                int c4   = idx & 31;
                unsigned grow = (unsigned)(row0 + row);
                unsigned node = grow / KNB;
                float4 n = nbr4[(size_t)grow * 32 + c4];
                float4 e = extra4[(size_t)node * 32 + c4];
                float x0 = n.x * e.x, x1 = n.y * e.y, x2 = n.z * e.z, x3 = n.w * e.w;
                uint32_t p01, p23;
                asm("cvt.rn.f16x2.f32 %0, %1, %2;" : "=r"(p01) : "f"(x1), "f"(x0));
                asm("cvt.rn.f16x2.f32 %0, %1, %2;" : "=r"(p23) : "f"(x3), "f"(x2));
                uint32_t off = sw_off(row, c4 >> 1) + (c4 & 1) * 8;
                asm volatile("st.shared.v2.b32 [%0], {%1,%2};"
                             :: "r"(aBuf + off), "r"(p01), "r"(p23));
            }
            BAR_ARRIVE(BAR_READY0 + b);
        }
    } else {
        const int wm = w & 3;
        const int wn = w >> 2;
        const int aRow = wm * 32 + (lane & 15);
        const int aCb  = lane >> 4;
        const int aXor = aRow & 7;
        const int bNl  = ((lane >> 4) << 3) + (lane & 7);
        const int bCb  = (lane >> 3) & 1;
        const int bXor = lane & 7;
        const uint32_t nBase = (uint32_t)((wn * 64 + bNl) * 256);

        int it = 0;
        for (int sup = blockIdx.x; sup < NSUP; sup += GRID1, ++it) {
            const int b = (it >= 3) ? (it % 3) : it;
            BAR_SYNC(BAR_READY0 + b);
            const uint32_t aBase = sb + SM_A0 + b * 32768 + aRow * 256;
            const int row0 = sup * 128;

            float acc[2][8][4];
            #pragma unroll
            for (int mi = 0; mi < 2; ++mi)
                #pragma unroll
                for (int ni = 0; ni < 8; ++ni)
                    { acc[mi][ni][0]=acc[mi][ni][1]=acc[mi][ni][2]=acc[mi][ni][3]=0.f; }

            #pragma unroll
            for (int ks = 0; ks < 8; ++ks) {
                uint32_t a0[4], a1[4];
                uint32_t koffA = (uint32_t)(((2 * ks + aCb) ^ aXor) << 4);
                LDSM4(a0, aBase + koffA);
                LDSM4(a1, aBase + 4096 + koffA);
                uint32_t kc = (uint32_t)(((2 * ks + bCb) ^ bXor) << 4);
                #pragma unroll
                for (int j = 0; j < 4; ++j) {
                    uint32_t bh[4];
                    LDSM4(bh, sb + SM_W + nBase + (uint32_t)(j * 16 * 256) + kc);
                    MMA_F16(acc[0][2*j],   a0, bh);
                    MMA_F16(acc[0][2*j+1], a0, bh + 2);
                    MMA_F16(acc[1][2*j],   a1, bh);
                    MMA_F16(acc[1][2*j+1], a1, bh + 2);
                }
            }
            BAR_ARRIVE(BAR_FREE0 + b);

            const int grp = lane >> 2, qid = lane & 3;
            #pragma unroll
            for (int mi = 0; mi < 2; ++mi) {
                const int rowA = wm * 32 + mi * 16 + grp;
                const float wrA = __ldg(&wgt[row0 + rowA]);
                const float wrB = __ldg(&wgt[row0 + rowA + 8]);
                float pa = 0.f, pb = 0.f;
                #pragma unroll
                for (int ni = 0; ni < 8; ++ni) {
                    int c = wn * 64 + ni * 8 + qid * 2;
                    float b0 = s_w1b[c], b1 = s_w1b[c + 1];
                    float u0 = s_w2[c],  u1 = s_w2[c + 1];
                    float v;
                    v = acc[mi][ni][0] + wrA * b0; v = (v >= 0.f) ? v : 0.2f * v; pa += v * u0;
                    v = acc[mi][ni][1] + wrA * b1; v = (v >= 0.f) ? v : 0.2f * v; pa += v * u1;
                    v = acc[mi][ni][2] + wrB * b0; v = (v >= 0.f) ? v : 0.2f * v; pb += v * u0;
                    v = acc[mi][ni][3] + wrB * b1; v = (v >= 0.f) ? v : 0.2f * v; pb += v * u1;
                }
                pa += __shfl_xor_sync(0xffffffffu, pa, 1);
                pa += __shfl_xor_sync(0xffffffffu, pa, 2);
                pb += __shfl_xor_sync(0xffffffffu, pb, 1);
                pb += __shfl_xor_sync(0xffffffffu, pb, 2);
                if (qid == 0) {
                    s_part[rowA * 2 + wn]       = pa;
                    s_part[(rowA + 8) * 2 + wn] = pb;
                }
            }
            BAR_SYNC_C(BAR_CONS);
            if (wn == 0) {
                const int row = wm * 32 + lane;
                g_logits[row0 + row] = s_part[row * 2] + s_part[row * 2 + 1];
            }
            BAR_SYNC_C(BAR_CONS);
        }
    }
}

// ===========================================================================
// K23 fused (512 threads, 16 warps): per 128-node tile:
//   softmax(g_logits) -> p ; A = [fp16(self) | fp16(sum_k p*nbr)] ;
//   out = relu(A @ w3^T fp16)
// GEMM warp tile 32x32 (4x4 warp grid). A rows 512B, XOR swizzled.
// ===========================================================================
#define SM23_W  0                   // w3^T fp16 (64KB)
#define SM23_A  65536               // A fp16 tile (64KB)
#define SM23_P  131072              // probs 128*12 f32 (6KB)
#define SMEM23  (131072 + 6144)
#define NT23    (NODES / 128)       // 256 tiles

extern "C" __global__ void __launch_bounds__(512, 1)
fused_out_kernel(const float* __restrict__ nbr,
                 const float* __restrict__ selfv,
                 const float* __restrict__ w3,
                 float* __restrict__ out)
{
    extern __shared__ __align__(1024) char smem[];
    const int t    = threadIdx.x;
    const int lane = t & 31;
    const int w    = t >> 5;
    const uint32_t sb = smem_u32(smem);
    float* s_p = (float*)(smem + SM23_P);

    // ---- stage w3^T (Wt[n][k], k 0..255) fp16, swizzled (once) ----
    #pragma unroll 4
    for (int i = 0; i < 64; ++i) {
        int idx = t + i * 512;                 // 32768 = 256*128
        int n = idx >> 8, k = idx & 255;
        __half hx = __float2half_rn(w3[k * 128 + n]);
        uint32_t off = (uint32_t)(n * 512 + (((k >> 3) ^ (n & 7)) << 4) + (k & 7) * 2);
        asm volatile("st.shared.u16 [%0], %1;" :: "r"(sb + SM23_W + off),
                     "h"(__half_as_ushort(hx)));
    }

    const int wm = w >> 2;                     // 0..3: rows
    const int wn = w & 3;                      // 0..3: cols
    const int aRow = wm * 32 + (lane & 15);
    const int aCb  = lane >> 4;
    const int aXor = aRow & 7;
    const int bNl  = ((lane >> 4) << 3) + (lane & 7);
    const int bCb  = (lane >> 3) & 1;
    const int bXor = lane & 7;
    const uint32_t nBase = (uint32_t)((wn * 32 + bNl) * 512);
    const uint32_t aBase = sb + SM23_A + aRow * 512;

    const float4* nbr4  = (const float4*)nbr;
    const float4* self4 = (const float4*)selfv;

    for (int tile = blockIdx.x; tile < NT23; tile += GRID1) {
        const int node0 = tile * 128;
        __syncthreads();                        // A/probs safe to overwrite

        // ---- softmax for 128 nodes (threads 0..127) ----
        if (t < 128) {
            const int base = (node0 + t) * KNB;
            float lg[KNB];
            float m = -1e30f;
            #pragma unroll
            for (int k = 0; k < KNB; ++k) { lg[k] = g_logits[base + k]; m = fmaxf(m, lg[k]); }
            float sum = 0.f;
            #pragma unroll
            for (int k = 0; k < KNB; ++k) { lg[k] = __expf(lg[k] - m); sum += lg[k]; }
            const float inv = 1.0f / sum;
            #pragma unroll
            for (int k = 0; k < KNB; ++k) s_p[t * KNB + k] = lg[k] * inv;
        }

        // ---- self -> A[k 0..127] fp16 swizzled (512 thr, 8 iters) ----
        #pragma unroll 4
        for (int i = 0; i < 8; ++i) {
            int idx = t + i * 512;              // 4096 = 128 rows x 32 c4
            int row = idx >> 5;
            int c4  = idx & 31;
            float4 v = self4[(size_t)(node0 + row) * 32 + c4];
            uint32_t p01, p23;
            asm("cvt.rn.f16x2.f32 %0, %1, %2;" : "=r"(p01) : "f"(v.y), "f"(v.x));
            asm("cvt.rn.f16x2.f32 %0, %1, %2;" : "=r"(p23) : "f"(v.w), "f"(v.z));
            uint32_t off = (uint32_t)(row * 512 + (((c4 >> 1) ^ (row & 7)) << 4)
                                      + (c4 & 1) * 8);
            asm volatile("st.shared.v2.b32 [%0], {%1,%2};"
                         :: "r"(sb + SM23_A + off), "r"(p01), "r"(p23));
        }
        __syncthreads();                        // probs ready

        // ---- agg -> A[k 128..255] (512 thr, 8 iters, 12 indep LDG.128 each) ----
        #pragma unroll 1
        for (int i = 0; i < 8; ++i) {
            int idx = t + i * 512;              // 4096 = 128 nodes x 32 c4
            int row = idx >> 5;                 // node-local (warp-uniform)
            int c4  = idx & 31;
            const float* pp = s_p + row * KNB;
            const float4* nb = nbr4 + ((size_t)(node0 + row) * KNB) * 32 + c4;
            float4 agg = make_float4(0.f, 0.f, 0.f, 0.f);
            #pragma unroll
            for (int k = 0; k < KNB; ++k) {
                float pk = pp[k];
                float4 r = nb[k * 32];
                agg.x += pk * r.x; agg.y += pk * r.y;
                agg.z += pk * r.z; agg.w += pk * r.w;
            }
            uint32_t p01, p23;
            asm("cvt.rn.f16x2.f32 %0, %1, %2;" : "=r"(p01) : "f"(agg.y), "f"(agg.x));
            asm("cvt.rn.f16x2.f32 %0, %1, %2;" : "=r"(p23) : "f"(agg.w), "f"(agg.z));
            uint32_t off = (uint32_t)(row * 512 + ((((c4 >> 1) + 16) ^ (row & 7)) << 4)
                                      + (c4 & 1) * 8);
            asm volatile("st.shared.v2.b32 [%0], {%1,%2};"
                         :: "r"(sb + SM23_A + off), "r"(p01), "r"(p23));
        }
        __syncthreads();                        // A complete

        // ---- GEMM 128x128x256 fp16, 16 warps x (32x32) ----
        float acc[2][4][4];
        #pragma unroll
        for (int mi = 0; mi < 2; ++mi)
            #pragma unroll
            for (int ni = 0; ni < 4; ++ni)
                { acc[mi][ni][0]=acc[mi][ni][1]=acc[mi][ni][2]=acc[mi][ni][3]=0.f; }

        #pragma unroll
        for (int ks = 0; ks < 16; ++ks) {
            uint32_t a0[4], a1[4];
            uint32_t koffA = (uint32_t)(((2 * ks + aCb) ^ aXor) << 4);
            LDSM4(a0, aBase + koffA);
            LDSM4(a1, aBase + 8192 + koffA);    // rows +16 (512B rows)
            const uint32_t kc = (uint32_t)(((2 * ks + bCb) ^ bXor) << 4);
            #pragma unroll
            for (int j = 0; j < 2; ++j) {
                uint32_t bh[4];
                LDSM4(bh, sb + SM23_W + nBase + (uint32_t)(j * 16 * 512) + kc);
                MMA_F16(acc[0][2*j],   a0, bh);
                MMA_F16(acc[0][2*j+1], a0, bh + 2);
                MMA_F16(acc[1][2*j],   a1, bh);
                MMA_F16(acc[1][2*j+1], a1, bh + 2);
            }
        }

        // ---- relu + store ----
        const int grp = lane >> 2, qid = lane & 3;
        #pragma unroll
        for (int mi = 0; mi < 2; ++mi) {
            const int rowg = node0 + wm * 32 + mi * 16 + grp;
            #pragma unroll
            for (int ni = 0; ni < 4; ++ni) {
                int col = wn * 32 + ni * 8 + qid * 2;
                float2 o0, o1;
                o0.x = fmaxf(acc[mi][ni][0], 0.f); o0.y = fmaxf(acc[mi][ni][1], 0.f);
                o1.x = fmaxf(acc[mi][ni][2], 0.f); o1.y = fmaxf(acc[mi][ni][3], 0.f);
                *(float2*)(out + (size_t)rowg * 128 + col)       = o0;
                *(float2*)(out + (size_t)(rowg + 8) * 128 + col) = o1;
            }
        }
    }
}

// ---------------------------------------------------------------------------
extern "C" void kernel_launch(void* const* d_in, const int* in_sizes, int n_in,
                              void* d_out, int out_size)
{
    int idx = 0;
    const float* selfv = (const float*)d_in[idx++];
    const float* nbr   = (const float*)d_in[idx++];
    if (idx < n_in && in_sizes[idx] == 1) idx++;   // batch_size scalar
    idx++;                                         // masks (unused)
    const float* wgt   = (const float*)d_in[idx++];
    const float* extra = (const float*)d_in[idx++];
    const float* w1    = (const float*)d_in[idx++];
    const float* w2    = (const float*)d_in[idx++];
    const float* w3    = (const float*)d_in[idx++];
    float* out = (float*)d_out;

    cudaFuncSetAttribute(logits_kernel,    cudaFuncAttributeMaxDynamicSharedMemorySize, SMEM1);
    cudaFuncSetAttribute(fused_out_kernel, cudaFuncAttributeMaxDynamicSharedMemorySize, SMEM23);

    logits_kernel<<<GRID1, 512, SMEM1>>>(nbr, wgt, extra, w1, w2);
    fused_out_kernel<<<GRID1, 512, SMEM23>>>(nbr, selfv, w3, out);
    (void)out_size; (void)n_in;
}